// round 3
// baseline (speedup 1.0000x reference)
#include <cuda_runtime.h>
#include <math.h>

#define D 1024
#define D4 256          // D / 4
#define NROWS 50000
#define BPM 148         // blocks per module, main pass
#define KCHUNKS 32      // k-split chunks for vecmat
#define KROWS (D / KCHUNKS)

// ---------------- scratch (device globals; no allocation allowed) -----------
__device__ float g_vm_partial[2][KCHUNKS][D]; // vecmat partials (reused twice)
__device__ float g_bw[2][D];                  // b_w per module
__device__ float g_main_partial[2][BPM][D];   // weighted-sum partials
__device__ float g_main_alpha[2][BPM];        // alpha-sum partials
__device__ float g_so[2][D];                  // sum_output per module
__device__ float g_attn[2 * D];               // concat(res_in, res_out)

// ---------------- vecmat: y[d] = sum_k v[k] * M[k*D + d], k-split ----------
__global__ void vecmat_partial(const float* __restrict__ v0,
                               const float* __restrict__ M0,
                               const float* __restrict__ v1,
                               const float* __restrict__ M1,
                               int useSO) {
    int vec = blockIdx.y;
    const float* v = useSO ? g_so[vec] : (vec ? v1 : v0);
    const float4* M4 = (const float4*)(vec ? M1 : M0);
    int t = threadIdx.x;        // 0..255
    int k0 = blockIdx.x * KROWS;
    float4 acc = make_float4(0.f, 0.f, 0.f, 0.f);
#pragma unroll 8
    for (int kk = 0; kk < KROWS; kk++) {
        float vk = __ldg(v + k0 + kk);
        float4 m = M4[(size_t)(k0 + kk) * D4 + t];
        acc.x = fmaf(vk, m.x, acc.x);
        acc.y = fmaf(vk, m.y, acc.y);
        acc.z = fmaf(vk, m.z, acc.z);
        acc.w = fmaf(vk, m.w, acc.w);
    }
    ((float4*)g_vm_partial[vec][blockIdx.x])[t] = acc;
}

// which==0 -> write g_bw, which==1 -> write g_attn
__global__ void vecmat_reduce(int which) {
    int vec = blockIdx.x;
    int t = threadIdx.x;
    float4 acc = make_float4(0.f, 0.f, 0.f, 0.f);
#pragma unroll
    for (int c = 0; c < KCHUNKS; c++) {
        float4 p = ((const float4*)g_vm_partial[vec][c])[t];
        acc.x += p.x; acc.y += p.y; acc.z += p.z; acc.w += p.w;
    }
    float* out = which ? &g_attn[vec * D] : g_bw[vec];
    ((float4*)out)[t] = acc;
}

// ---------------- main single-pass kernel -----------------------------------
// warp-per-row: s = X_j . b_w ; alpha = exp(s) ; acc += alpha * X_j
__global__ void __launch_bounds__(256, 2)
main_pass(const float* __restrict__ Xin, const float* __restrict__ Xout, int nrows) {
    int mod = blockIdx.y;
    const float4* X4 = (const float4*)(mod ? Xout : Xin);

    __shared__ float4 s_bw[D4];
    __shared__ float4 s_red[8 * D4];
    __shared__ float  s_alpha[8];

    int t = threadIdx.x;
    s_bw[t] = ((const float4*)g_bw[mod])[t];
    __syncthreads();

    int warp = t >> 5, lane = t & 31;
    int gw = blockIdx.x * 8 + warp;
    const int NW = BPM * 8;

    float4 acc[8];
#pragma unroll
    for (int i = 0; i < 8; i++) acc[i] = make_float4(0.f, 0.f, 0.f, 0.f);
    float asum = 0.f;

    for (int row = gw; row < nrows; row += NW) {
        const float4* xr = X4 + (size_t)row * D4;
        float4 r[8];
#pragma unroll
        for (int i = 0; i < 8; i++) r[i] = xr[lane + 32 * i];

        float s = 0.f;
#pragma unroll
        for (int i = 0; i < 8; i++) {
            float4 b = s_bw[lane + 32 * i];
            s = fmaf(r[i].x, b.x, s);
            s = fmaf(r[i].y, b.y, s);
            s = fmaf(r[i].z, b.z, s);
            s = fmaf(r[i].w, b.w, s);
        }
#pragma unroll
        for (int o = 16; o > 0; o >>= 1)
            s += __shfl_xor_sync(0xffffffffu, s, o);

        float alpha = __expf(s);   // identical across all 32 lanes (full butterfly)
        asum += alpha;             // per-lane asum == warp total (do NOT reduce again)
#pragma unroll
        for (int i = 0; i < 8; i++) {
            acc[i].x = fmaf(alpha, r[i].x, acc[i].x);
            acc[i].y = fmaf(alpha, r[i].y, acc[i].y);
            acc[i].z = fmaf(alpha, r[i].z, acc[i].z);
            acc[i].w = fmaf(alpha, r[i].w, acc[i].w);
        }
    }

    // deterministic block reduce: warp -> smem slot, fixed-order sum
#pragma unroll
    for (int i = 0; i < 8; i++) s_red[warp * D4 + lane + 32 * i] = acc[i];
    // asum is already the warp total on every lane (alpha was lane-uniform).
    // R2 fix: previous kernel butterfly-reduced it again -> 32x inflation.
    if (lane == 0) s_alpha[warp] = asum;
    __syncthreads();

    float4 tot = make_float4(0.f, 0.f, 0.f, 0.f);
#pragma unroll
    for (int w = 0; w < 8; w++) {
        float4 v = s_red[w * D4 + t];
        tot.x += v.x; tot.y += v.y; tot.z += v.z; tot.w += v.w;
    }
    ((float4*)g_main_partial[mod][blockIdx.x])[t] = tot;
    if (t == 0) {
        float a = 0.f;
#pragma unroll
        for (int w = 0; w < 8; w++) a += s_alpha[w];
        g_main_alpha[mod][blockIdx.x] = a;
    }
}

// ---------------- reduce main partials -> g_so = weighted / sum(alpha) ------
// grid (8 col-chunks, 2 modules), 256 threads = 8 groups x 32 cols(float4)
__global__ void main_reduce() {
    int mod = blockIdx.y;
    int cb = blockIdx.x;                 // 0..7
    int t = threadIdx.x;
    int lane32 = t & 31;
    int grp = t >> 5;                    // 0..7
    int c4 = cb * 32 + lane32;           // float4 column index 0..255

    __shared__ float4 s_part[8][32];
    __shared__ float  s_a[256];

    // alpha total (deterministic fixed-order tree)
    float a = 0.f;
    for (int b = t; b < BPM; b += 256) a += g_main_alpha[mod][b];
    s_a[t] = a;
    __syncthreads();
    for (int o = 128; o > 0; o >>= 1) {
        if (t < o) s_a[t] += s_a[t + o];
        __syncthreads();
    }
    float inv = 1.0f / s_a[0];

    float4 acc = make_float4(0.f, 0.f, 0.f, 0.f);
    for (int b = grp; b < BPM; b += 8) {
        float4 v = ((const float4*)g_main_partial[mod][b])[c4];
        acc.x += v.x; acc.y += v.y; acc.z += v.z; acc.w += v.w;
    }
    s_part[grp][lane32] = acc;
    __syncthreads();
    if (grp == 0) {
        float4 totv = s_part[0][lane32];
#pragma unroll
        for (int w = 1; w < 8; w++) {
            float4 v = s_part[w][lane32];
            totv.x += v.x; totv.y += v.y; totv.z += v.z; totv.w += v.w;
        }
        totv.x *= inv; totv.y *= inv; totv.z *= inv; totv.w *= inv;
        ((float4*)g_so[mod])[c4] = totv;
    }
}

// ---------------- final: out[i] = elu( lin_W[i,:] . attn + lin_b[i] ) -------
__global__ void final_kernel(const float* __restrict__ linW,
                             const float* __restrict__ linb,
                             float* __restrict__ out) {
    __shared__ float4 sa[2 * D4];        // 2048 floats of attn
    __shared__ float  sw[8];
    int t = threadIdx.x;
    sa[t]        = ((const float4*)g_attn)[t];
    sa[t + D4]   = ((const float4*)g_attn)[t + D4];
    __syncthreads();

    int i = blockIdx.x;
    const float4* row = (const float4*)linW + (size_t)i * (2 * D4);
    float4 w1 = row[t],        a1 = sa[t];
    float4 w2 = row[t + D4],   a2 = sa[t + D4];
    float s = 0.f;
    s = fmaf(w1.x, a1.x, s); s = fmaf(w1.y, a1.y, s);
    s = fmaf(w1.z, a1.z, s); s = fmaf(w1.w, a1.w, s);
    s = fmaf(w2.x, a2.x, s); s = fmaf(w2.y, a2.y, s);
    s = fmaf(w2.z, a2.z, s); s = fmaf(w2.w, a2.w, s);

#pragma unroll
    for (int o = 16; o > 0; o >>= 1)
        s += __shfl_xor_sync(0xffffffffu, s, o);
    int warp = t >> 5, lane = t & 31;
    if (lane == 0) sw[warp] = s;
    __syncthreads();
    if (t == 0) {
        float tot = 0.f;
#pragma unroll
        for (int w = 0; w < 8; w++) tot += sw[w];
        tot += linb[i];
        out[i] = tot > 0.f ? tot : expm1f(tot);   // jax.nn.elu, alpha=1
    }
}

// ---------------- launcher ---------------------------------------------------
extern "C" void kernel_launch(void* const* d_in, const int* in_sizes, int n_in,
                              void* d_out, int out_size) {
    const float* X_in      = (const float*)d_in[0];
    const float* X_out     = (const float*)d_in[1];
    const float* W_alpha_i = (const float*)d_in[2];
    // d_in[3] = a_alpha_in : unused (constant cancels in normalization)
    const float* b_alpha_i = (const float*)d_in[4];
    const float* W_sum_i   = (const float*)d_in[5];
    const float* W_alpha_o = (const float*)d_in[6];
    // d_in[7] = a_alpha_out : unused
    const float* b_alpha_o = (const float*)d_in[8];
    const float* W_sum_o   = (const float*)d_in[9];
    const float* lin_W     = (const float*)d_in[10];
    const float* lin_b     = (const float*)d_in[11];
    float* out = (float*)d_out;

    int nrows = in_sizes[0] / D;   // 50000

    // 1) b_w = b_alpha^T @ W_alpha (both modules)
    vecmat_partial<<<dim3(KCHUNKS, 2), 256>>>(b_alpha_i, W_alpha_i,
                                              b_alpha_o, W_alpha_o, 0);
    vecmat_reduce<<<2, 256>>>(0);

    // 2) single pass over X: alpha + weighted sum (both modules)
    main_pass<<<dim3(BPM, 2), 256>>>(X_in, X_out, nrows);

    // 3) partials -> sum_output = weighted / sum(alpha)
    main_reduce<<<dim3(8, 2), 256>>>();

    // 4) res = sum_output @ W_sum (both modules) -> g_attn (concat)
    vecmat_partial<<<dim3(KCHUNKS, 2), 256>>>(nullptr, W_sum_i,
                                              nullptr, W_sum_o, 1);
    vecmat_reduce<<<2, 256>>>(1);

    // 5) out = elu(attn @ lin_W^T + lin_b)
    final_kernel<<<D, 256>>>(lin_W, lin_b, out);
}

// round 4
// speedup vs baseline: 1.0869x; 1.0869x over previous
#include <cuda_runtime.h>
#include <math.h>

#define D 1024
#define D4 256          // D / 4
#define NROWS 50000
#define BPM 148         // blocks per module, main pass
#define KCHUNKS 64      // k-split chunks for vecmat
#define KROWS (D / KCHUNKS)

typedef unsigned long long u64;

// ---------------- scratch (device globals; no allocation allowed) -----------
__device__ float g_vm_partial[2][KCHUNKS][D]; // vecmat partials (reused twice)
__device__ float g_bw[2][D];                  // b_w per module
__device__ float g_main_partial[2][BPM][D];   // weighted-sum partials
__device__ float g_main_alpha[2][BPM];        // alpha-sum partials
__device__ float g_so[2][D];                  // sum_output per module
__device__ float g_attn[2 * D];               // concat(res_in, res_out)

// packed f32x2 FMA: d = a*b + d   (SASS FFMA2; PTX-only form)
__device__ __forceinline__ void fma2(u64& d, u64 a, u64 b) {
    asm("fma.rn.f32x2 %0, %1, %2, %0;" : "+l"(d) : "l"(a), "l"(b));
}
__device__ __forceinline__ u64 pack2(float lo, float hi) {
    u64 r;
    asm("mov.b64 %0, {%1, %2};" : "=l"(r) : "f"(lo), "f"(hi));
    return r;
}
__device__ __forceinline__ void unpack2(float& lo, float& hi, u64 v) {
    asm("mov.b64 {%0, %1}, %2;" : "=f"(lo), "=f"(hi) : "l"(v));
}

// ---------------- vecmat: y[d] = sum_k v[k] * M[k*D + d], k-split ----------
__global__ void vecmat_partial(const float* __restrict__ v0,
                               const float* __restrict__ M0,
                               const float* __restrict__ v1,
                               const float* __restrict__ M1,
                               int useSO) {
    int vec = blockIdx.y;
    const float* v = useSO ? g_so[vec] : (vec ? v1 : v0);
    const float4* M4 = (const float4*)(vec ? M1 : M0);
    int t = threadIdx.x;        // 0..255
    int k0 = blockIdx.x * KROWS;
    float4 acc = make_float4(0.f, 0.f, 0.f, 0.f);
#pragma unroll
    for (int kk = 0; kk < KROWS; kk++) {     // KROWS=16, fully unrolled -> MLP 16
        float vk = __ldg(v + k0 + kk);
        float4 m = M4[(size_t)(k0 + kk) * D4 + t];
        acc.x = fmaf(vk, m.x, acc.x);
        acc.y = fmaf(vk, m.y, acc.y);
        acc.z = fmaf(vk, m.z, acc.z);
        acc.w = fmaf(vk, m.w, acc.w);
    }
    ((float4*)g_vm_partial[vec][blockIdx.x])[t] = acc;
}

// which==0 -> write g_bw, which==1 -> write g_attn
__global__ void vecmat_reduce(int which) {
    int vec = blockIdx.x;
    int t = threadIdx.x;
    float4 acc = make_float4(0.f, 0.f, 0.f, 0.f);
#pragma unroll 8
    for (int c = 0; c < KCHUNKS; c++) {
        float4 p = ((const float4*)g_vm_partial[vec][c])[t];
        acc.x += p.x; acc.y += p.y; acc.z += p.z; acc.w += p.w;
    }
    float* out = which ? &g_attn[vec * D] : g_bw[vec];
    ((float4*)out)[t] = acc;
}

// ---------------- main single-pass kernel -----------------------------------
// warp-per-row: s = X_j . b_w ; alpha = exp(s) ; acc += alpha * X_j
// f32x2 packed FMA everywhere; b_w resident in registers (no per-row LDS).
__global__ void __launch_bounds__(256, 2)
main_pass(const float* __restrict__ Xin, const float* __restrict__ Xout, int nrows) {
    int mod = blockIdx.y;
    const ulonglong2* X2 = (const ulonglong2*)(mod ? Xout : Xin); // 16B units, 256/row

    __shared__ float4 s_red[8 * D4];
    __shared__ float  s_alpha[8];

    int t = threadIdx.x, warp = t >> 5, lane = t & 31;

    // b_w slice for this lane: float4 columns lane+32*i, i=0..7 -> 16 u64
    u64 bw[16];
    {
        const ulonglong2* B2 = (const ulonglong2*)g_bw[mod];
#pragma unroll
        for (int i = 0; i < 8; i++) {
            ulonglong2 v = B2[lane + 32 * i];
            bw[2 * i] = v.x; bw[2 * i + 1] = v.y;
        }
    }

    u64 acc[16];
#pragma unroll
    for (int i = 0; i < 16; i++) acc[i] = 0ull;   // bit pattern of (0.f,0.f)
    float asum = 0.f;

    int gw = blockIdx.x * 8 + warp;
    const int NW = BPM * 8;

    for (int row = gw; row < nrows; row += NW) {
        const ulonglong2* xr = X2 + (size_t)row * 256;
        u64 r[16];
#pragma unroll
        for (int i = 0; i < 8; i++) {             // 8 LDG.128 front-batched
            ulonglong2 v = xr[lane + 32 * i];
            r[2 * i] = v.x; r[2 * i + 1] = v.y;
        }

        // dot: two independent f32x2 chains for ILP
        u64 d0 = 0ull, d1 = 0ull;
#pragma unroll
        for (int i = 0; i < 8; i++) {
            fma2(d0, r[2 * i],     bw[2 * i]);
            fma2(d1, r[2 * i + 1], bw[2 * i + 1]);
        }
        float a0, a1, b0, b1;
        unpack2(a0, a1, d0);
        unpack2(b0, b1, d1);
        float s = (a0 + a1) + (b0 + b1);
#pragma unroll
        for (int o = 16; o > 0; o >>= 1)
            s += __shfl_xor_sync(0xffffffffu, s, o);

        float alpha = __expf(s);                  // lane-uniform after butterfly
        asum += alpha;                            // per-lane asum == warp total
        u64 alpha2 = pack2(alpha, alpha);
#pragma unroll
        for (int i = 0; i < 16; i++) fma2(acc[i], alpha2, r[i]);
    }

    // deterministic block reduce: warp -> smem slot, fixed-order sum
#pragma unroll
    for (int i = 0; i < 8; i++) {
        float x, y, z, w;
        unpack2(x, y, acc[2 * i]);
        unpack2(z, w, acc[2 * i + 1]);
        s_red[warp * D4 + lane + 32 * i] = make_float4(x, y, z, w);
    }
    if (lane == 0) s_alpha[warp] = asum;          // asum already warp-total
    __syncthreads();

    float4 tot = make_float4(0.f, 0.f, 0.f, 0.f);
#pragma unroll
    for (int w = 0; w < 8; w++) {
        float4 v = s_red[w * D4 + t];
        tot.x += v.x; tot.y += v.y; tot.z += v.z; tot.w += v.w;
    }
    ((float4*)g_main_partial[mod][blockIdx.x])[t] = tot;
    if (t == 0) {
        float a = 0.f;
#pragma unroll
        for (int w = 0; w < 8; w++) a += s_alpha[w];
        g_main_alpha[mod][blockIdx.x] = a;
    }
}

// ---------------- reduce main partials -> g_so = weighted / sum(alpha) ------
// warp-per-float4-column: grid (32, 2), 256 threads = 8 warps = 8 columns/block
__global__ void main_reduce() {
    int mod = blockIdx.y;
    int t = threadIdx.x, warp = t >> 5, lane = t & 31;
    int c4 = blockIdx.x * 8 + warp;               // float4 column 0..255

    __shared__ float s_inv;

    if (warp == 0) {                              // alpha total (fixed-order butterfly)
        float a = 0.f;
        for (int b = lane; b < BPM; b += 32) a += g_main_alpha[mod][b];
#pragma unroll
        for (int o = 16; o > 0; o >>= 1)
            a += __shfl_xor_sync(0xffffffffu, a, o);
        if (lane == 0) s_inv = 1.0f / a;
    }

    float4 acc = make_float4(0.f, 0.f, 0.f, 0.f);
    for (int b = lane; b < BPM; b += 32) {        // 5 independent LDG.128 per lane
        float4 v = ((const float4*)g_main_partial[mod][b])[c4];
        acc.x += v.x; acc.y += v.y; acc.z += v.z; acc.w += v.w;
    }
#pragma unroll
    for (int o = 16; o > 0; o >>= 1) {
        acc.x += __shfl_xor_sync(0xffffffffu, acc.x, o);
        acc.y += __shfl_xor_sync(0xffffffffu, acc.y, o);
        acc.z += __shfl_xor_sync(0xffffffffu, acc.z, o);
        acc.w += __shfl_xor_sync(0xffffffffu, acc.w, o);
    }
    __syncthreads();
    if (lane == 0) {
        float inv = s_inv;
        acc.x *= inv; acc.y *= inv; acc.z *= inv; acc.w *= inv;
        ((float4*)g_so[mod])[c4] = acc;
    }
}

// ---------------- final: out[i] = elu( lin_W[i,:] . attn + lin_b[i] ) -------
__global__ void final_kernel(const float* __restrict__ linW,
                             const float* __restrict__ linb,
                             float* __restrict__ out) {
    __shared__ float4 sa[2 * D4];        // 2048 floats of attn
    __shared__ float  sw[8];
    int t = threadIdx.x;
    sa[t]        = ((const float4*)g_attn)[t];
    sa[t + D4]   = ((const float4*)g_attn)[t + D4];
    __syncthreads();

    int i = blockIdx.x;
    const float4* row = (const float4*)linW + (size_t)i * (2 * D4);
    float4 w1 = row[t],        a1 = sa[t];
    float4 w2 = row[t + D4],   a2 = sa[t + D4];
    float s = 0.f;
    s = fmaf(w1.x, a1.x, s); s = fmaf(w1.y, a1.y, s);
    s = fmaf(w1.z, a1.z, s); s = fmaf(w1.w, a1.w, s);
    s = fmaf(w2.x, a2.x, s); s = fmaf(w2.y, a2.y, s);
    s = fmaf(w2.z, a2.z, s); s = fmaf(w2.w, a2.w, s);

#pragma unroll
    for (int o = 16; o > 0; o >>= 1)
        s += __shfl_xor_sync(0xffffffffu, s, o);
    int warp = t >> 5, lane = t & 31;
    if (lane == 0) sw[warp] = s;
    __syncthreads();
    if (t == 0) {
        float tot = 0.f;
#pragma unroll
        for (int w = 0; w < 8; w++) tot += sw[w];
        tot += linb[i];
        out[i] = tot > 0.f ? tot : expm1f(tot);   // jax.nn.elu, alpha=1
    }
}

// ---------------- launcher ---------------------------------------------------
extern "C" void kernel_launch(void* const* d_in, const int* in_sizes, int n_in,
                              void* d_out, int out_size) {
    const float* X_in      = (const float*)d_in[0];
    const float* X_out     = (const float*)d_in[1];
    const float* W_alpha_i = (const float*)d_in[2];
    // d_in[3] = a_alpha_in : unused (constant cancels in normalization)
    const float* b_alpha_i = (const float*)d_in[4];
    const float* W_sum_i   = (const float*)d_in[5];
    const float* W_alpha_o = (const float*)d_in[6];
    // d_in[7] = a_alpha_out : unused
    const float* b_alpha_o = (const float*)d_in[8];
    const float* W_sum_o   = (const float*)d_in[9];
    const float* lin_W     = (const float*)d_in[10];
    const float* lin_b     = (const float*)d_in[11];
    float* out = (float*)d_out;

    int nrows = in_sizes[0] / D;   // 50000

    // 1) b_w = b_alpha^T @ W_alpha (both modules)
    vecmat_partial<<<dim3(KCHUNKS, 2), 256>>>(b_alpha_i, W_alpha_i,
                                              b_alpha_o, W_alpha_o, 0);
    vecmat_reduce<<<2, 256>>>(0);

    // 2) single pass over X: alpha + weighted sum (both modules)
    main_pass<<<dim3(BPM, 2), 256>>>(X_in, X_out, nrows);

    // 3) partials -> sum_output = weighted / sum(alpha)
    main_reduce<<<dim3(32, 2), 256>>>();

    // 4) res = sum_output @ W_sum (both modules) -> g_attn (concat)
    vecmat_partial<<<dim3(KCHUNKS, 2), 256>>>(nullptr, W_sum_i,
                                              nullptr, W_sum_o, 1);
    vecmat_reduce<<<2, 256>>>(1);

    // 5) out = elu(attn @ lin_W^T + lin_b)
    final_kernel<<<D, 256>>>(lin_W, lin_b, out);
}